// round 16
// baseline (speedup 1.0000x reference)
#include <cuda_runtime.h>
#include <cuda_bf16.h>
#include <math.h>
#include <stdint.h>

// ----------------------------------------------------------------------------
// Attention_13314398617962   (t=512, b=64, s=1024, hu=1024)
//   scores[t,b] = MLP(concat(si[b], h[t,b]))   (2048 -> 10 -> 5 -> 1, BN+relu)
//   a = softmax(scores.flatten())              (over all 32768)
//   ci[b,:] = sum_tau a[tau] * h[tau_t, tau_b, :]   (tau < 512)
// ----------------------------------------------------------------------------

#define T_DIM 512
#define B_DIM 64
#define HU 1024
#define NROWS (T_DIM * B_DIM)   // 32768
#define RPB 8                   // rows per block in score kernel
#define NBLK (NROWS / RPB)      // 4096
#define THREADS 384             // 8 consumer warps + 4 producer warps

// dynamic smem: ring[8 rows * 1024] + red[8][128][10]  = 18432 floats (72 KB)
#define RING_FLOATS (RPB * 1024)
#define RED_FLOATS  (RPB * 128 * 10)
#define DYN_BYTES   ((RING_FLOATS + RED_FLOATS) * 4)

__device__ float g_pre0[B_DIM * 10];   // si @ W0[:1024] per b (raw dot)
__device__ float g_ep[30];             // s0[10] t0[10] s1[5] t1[5]
__device__ float g_scores[T_DIM];      // raw scores for rows < 512
__device__ float g_w[T_DIM];           // softmax weights
__device__ float g_bmax[NBLK];
__device__ float g_bsum[NBLK];

// ---------------------------------------------------------------------------
__device__ __forceinline__ void ffma2(unsigned long long& d,
                                      unsigned long long a,
                                      unsigned long long b)
{
    asm("fma.rn.f32x2 %0, %1, %2, %0;" : "+l"(d) : "l"(a), "l"(b));
}
__device__ __forceinline__ void fmul2(unsigned long long& d,
                                      unsigned long long a,
                                      unsigned long long b)
{
    asm("mul.rn.f32x2 %0, %1, %2;" : "=l"(d) : "l"(a), "l"(b));
}
__device__ __forceinline__ unsigned long long pack2(float x)
{
    unsigned long long r;
    asm("mov.b64 %0, {%1, %1};" : "=l"(r) : "f"(x));
    return r;
}
__device__ __forceinline__ void unpack2(unsigned long long v, float& lo, float& hi)
{
    asm("mov.b64 {%0, %1}, %2;" : "=f"(lo), "=f"(hi) : "l"(v));
}

// ---------------------------------------------------------------------------
// K0: per-b si contribution (coalesced W0 reads) + folded BN constants.
// ---------------------------------------------------------------------------
__global__ __launch_bounds__(256)
void prep_kernel(const float* __restrict__ si,
                 const float* __restrict__ W0,
                 const float* __restrict__ b0,
                 const float* __restrict__ g0,
                 const float* __restrict__ be0,
                 const float* __restrict__ m0,
                 const float* __restrict__ v0,
                 const float* __restrict__ b1,
                 const float* __restrict__ g1,
                 const float* __restrict__ be1,
                 const float* __restrict__ m1,
                 const float* __restrict__ v1)
{
    __shared__ float red[64][10];

    int b = blockIdx.x;
    int tid = threadIdx.x;
    int lane = tid & 31;
    int warp = tid >> 5;

    float wv[40];
    {
        const float4* wp = reinterpret_cast<const float4*>(W0 + 4 * tid * 10);
#pragma unroll
        for (int i = 0; i < 10; ++i)
            reinterpret_cast<float4*>(wv)[i] = wp[i];
    }
    float4 sv = reinterpret_cast<const float4*>(si + b * 1024)[tid];

    float pj[10];
#pragma unroll
    for (int j = 0; j < 10; ++j) {
        float a = sv.x * wv[j];
        a = fmaf(sv.y, wv[10 + j], a);
        a = fmaf(sv.z, wv[20 + j], a);
        a = fmaf(sv.w, wv[30 + j], a);
        pj[j] = a;
    }
#pragma unroll
    for (int j = 0; j < 10; ++j) {
        pj[j] += __shfl_xor_sync(0xffffffffu, pj[j], 16);
        pj[j] += __shfl_xor_sync(0xffffffffu, pj[j], 8);
    }
    if (lane < 8) {
#pragma unroll
        for (int j = 0; j < 10; ++j) red[warp * 8 + lane][j] = pj[j];
    }
    __syncthreads();

    if (tid < 10) {
        float s = 0.f;
#pragma unroll
        for (int q = 0; q < 64; ++q) s += red[q][tid];
        g_pre0[b * 10 + tid] = s;
    }

    if (b == 0) {
        if (tid >= 32 && tid < 42) {
            int i = tid - 32;
            float s = g0[i] * (1.0f / sqrtf(v0[i] + 1e-5f));
            g_ep[i] = s;
            g_ep[10 + i] = (b0[i] - m0[i]) * s + be0[i];
        } else if (tid >= 64 && tid < 69) {
            int i = tid - 64;
            float s = g1[i] * (1.0f / sqrtf(v1[i] + 1e-5f));
            g_ep[20 + i] = s;
            g_ep[25 + i] = (b1[i] - m1[i]) * s + be1[i];
        }
    }
}

// ---------------------------------------------------------------------------
// K1: scores + per-block online softmax stats. 8 rows/block, 4096 blocks.
// WARP SPECIALIZATION: threads 0..255 = 8 consumer warps; 256..383 = 4
// producer warps. Producers load ALL 8 rows (each producer warp: 2 rows x
// 8 warp-LDG.128 = 32 KB/CTA in flight at once -> DRAM latency fully
// hidden with zero consumer registers), STS into a linear smem ring, ONE
// __syncthreads. Consumers (thread ts owns k=4*ts, 40 weight floats as
// 20 packed f32x2) then process all 8 rows from smem: 1 LDS.128,
// 20 FFMA2, ONE shfl round, 3 STS.64 (lane<16). No other barriers.
// ~75-80 regs both paths -> __launch_bounds__(384,2) = 24 warps/SM.
// ---------------------------------------------------------------------------
__global__ __launch_bounds__(THREADS, 2)
void score_kernel(const float* __restrict__ h,
                  const float* __restrict__ W0,
                  const float* __restrict__ W1,
                  const float* __restrict__ W2,
                  const float* __restrict__ b2)
{
    extern __shared__ float dyn[];            // ring | red
    float* ring = dyn;                        // [row][1024]
    float* red  = dyn + RING_FLOATS;          // [row][part128][10]

    __shared__ float pre0s[RPB * 10];
    __shared__ float dsum[RPB * 10];
    __shared__ float epi[86];                 // s0 t0 s1 t1 W1[50] W2[5] b2

    int tid  = threadIdx.x;
    int lane = tid & 31;
    int warp = tid >> 5;
    int rowbase = blockIdx.x * RPB;
    int bbase   = rowbase & 63;

    if (tid < 30)                  epi[tid] = g_ep[tid];
    if (tid >= 32 && tid < 82)     epi[30 + tid - 32] = W1[tid - 32];
    if (tid >= 96 && tid < 101)    epi[80 + tid - 96] = W2[tid - 96];
    if (tid == 101)                epi[85] = b2[0];
    if (tid >= 128 && tid < 128 + RPB * 10)
        pre0s[tid - 128] = g_pre0[bbase * 10 + (tid - 128)];

    // consumer weights: 40 floats (k = 4*ts .. +3, all 10 j) as 20 f32x2
    union { float4 v[10]; unsigned long long u[20]; } wr;
    if (tid < 256) {
        const float4* wp = reinterpret_cast<const float4*>(W0 + (1024 + 4 * tid) * 10);
#pragma unroll
        for (int i = 0; i < 10; ++i) wr.v[i] = wp[i];
    }

    // ---------------- producers fill the ring ----------------
    if (tid >= 256) {
        int pw = warp - 8;        // 0..3
        int r0 = 2 * pw;          // two rows per producer warp
        const float4* h0 = reinterpret_cast<const float4*>(
            h + (size_t)(rowbase + r0) * 1024);
        const float4* h1 = reinterpret_cast<const float4*>(
            h + (size_t)(rowbase + r0 + 1) * 1024);
        float4 v0[8], v1[8];
#pragma unroll
        for (int c = 0; c < 8; ++c) v0[c] = h0[lane + 32 * c];
#pragma unroll
        for (int c = 0; c < 8; ++c) v1[c] = h1[lane + 32 * c];

        float4* s0 = reinterpret_cast<float4*>(ring + r0 * 1024);
        float4* s1 = reinterpret_cast<float4*>(ring + (r0 + 1) * 1024);
#pragma unroll
        for (int c = 0; c < 8; ++c) s0[lane + 32 * c] = v0[c];
#pragma unroll
        for (int c = 0; c < 8; ++c) s1[lane + 32 * c] = v1[c];
    }
    __syncthreads();

    // ---------------- consumers process 8 rows from smem ----------------
    if (tid < 256) {
        float* myred = red + (warp * 16 + (lane & 15)) * 10;
        const float4* myring = reinterpret_cast<const float4*>(ring) + tid;

#pragma unroll
        for (int it = 0; it < RPB; ++it) {
            float4 cv = myring[it * 256];

            unsigned long long acc[5];
            unsigned long long hh;
            hh = pack2(cv.x);
#pragma unroll
            for (int p = 0; p < 5; ++p) fmul2(acc[p], hh, wr.u[p]);
            hh = pack2(cv.y);
#pragma unroll
            for (int p = 0; p < 5; ++p) ffma2(acc[p], hh, wr.u[5 + p]);
            hh = pack2(cv.z);
#pragma unroll
            for (int p = 0; p < 5; ++p) ffma2(acc[p], hh, wr.u[10 + p]);
            hh = pack2(cv.w);
#pragma unroll
            for (int p = 0; p < 5; ++p) ffma2(acc[p], hh, wr.u[15 + p]);

            float pj[10];
#pragma unroll
            for (int p = 0; p < 5; ++p) unpack2(acc[p], pj[2 * p], pj[2 * p + 1]);

            // one shfl round: lanes<16 hold sums over {lane, lane+16}
#pragma unroll
            for (int j = 0; j < 10; ++j)
                pj[j] += __shfl_xor_sync(0xffffffffu, pj[j], 16);

            if (lane < 16) {
                float2* rb = reinterpret_cast<float2*>(myred + it * 1280);
#pragma unroll
                for (int p = 0; p < 5; ++p)
                    rb[p] = make_float2(pj[2 * p], pj[2 * p + 1]);
            }
        }
    }
    __syncthreads();

    // block reduce: 80 (row,j) sums, each over 128 partials (stride 10)
    if (tid < RPB * 10) {
        int rl = tid / 10;
        int j  = tid - rl * 10;
        const float* base = red + rl * 1280 + j;
        float s0 = 0.f, s1 = 0.f, s2 = 0.f, s3 = 0.f;
#pragma unroll
        for (int q = 0; q < 32; ++q) {
            s0 += base[(4 * q) * 10];
            s1 += base[(4 * q + 1) * 10];
            s2 += base[(4 * q + 2) * 10];
            s3 += base[(4 * q + 3) * 10];
        }
        dsum[tid] = (s0 + s1) + (s2 + s3);
    }
    __syncthreads();

    // fused MLP epilogue (8 rows) + warp-0 online softmax stats
    if (tid < 32) {
        float sc = -1e30f;
        if (tid < RPB) {
            int row = rowbase + tid;
            float x0[10];
#pragma unroll
            for (int j = 0; j < 10; ++j) {
                float d = dsum[tid * 10 + j] + pre0s[tid * 10 + j];
                x0[j] = fmaxf(fmaf(d, epi[j], epi[10 + j]), 0.f);
            }
            sc = epi[85];
#pragma unroll
            for (int i = 0; i < 5; ++i) {
                float z = 0.f;
#pragma unroll
                for (int j = 0; j < 10; ++j)
                    z = fmaf(x0[j], epi[30 + j * 5 + i], z);
                float x1 = fmaxf(fmaf(z, epi[20 + i], epi[25 + i]), 0.f);
                sc = fmaf(x1, epi[80 + i], sc);
            }
            if (row < T_DIM) g_scores[row] = sc;
        }
        float m = sc;
#pragma unroll
        for (int o = 16; o > 0; o >>= 1)
            m = fmaxf(m, __shfl_xor_sync(0xffffffffu, m, o));
        float e = (tid < RPB) ? expf(sc - m) : 0.f;
#pragma unroll
        for (int o = 16; o > 0; o >>= 1)
            e += __shfl_xor_sync(0xffffffffu, e, o);
        if (tid == 0) {
            g_bmax[blockIdx.x] = m;
            g_bsum[blockIdx.x] = e;
        }
    }
}

// ---------------------------------------------------------------------------
// K2: combine 4096 (max, expsum) pairs -> M, S; write 512 weights.
// ---------------------------------------------------------------------------
__global__ void combine_kernel()
{
    __shared__ float sm[512];
    __shared__ float MS[2];
    int tid = threadIdx.x;

    float lm = -1e30f;
    float bm[8];
#pragma unroll
    for (int i = 0; i < 8; ++i) {
        bm[i] = g_bmax[tid * 8 + i];
        lm = fmaxf(lm, bm[i]);
    }
    sm[tid] = lm;
    __syncthreads();
    for (int s = 256; s > 0; s >>= 1) {
        if (tid < s) sm[tid] = fmaxf(sm[tid], sm[tid + s]);
        __syncthreads();
    }
    if (tid == 0) MS[0] = sm[0];
    __syncthreads();
    float M = MS[0];

    float ls = 0.f;
#pragma unroll
    for (int i = 0; i < 8; ++i)
        ls += g_bsum[tid * 8 + i] * expf(bm[i] - M);
    sm[tid] = ls;
    __syncthreads();
    for (int s = 256; s > 0; s >>= 1) {
        if (tid < s) sm[tid] += sm[tid + s];
        __syncthreads();
    }
    if (tid == 0) MS[1] = 1.0f / sm[0];
    __syncthreads();

    g_w[tid] = expf(g_scores[tid] - M) * MS[1];
}

// ---------------------------------------------------------------------------
// K3: ci[b,:] = sum_tau w[tau] * h[tau,b,:]
// grid (8 chunks of 128 cols, 64 b) x 512 threads (16 warps, t == w mod 16).
// (best measured configuration, ~24 us)
// ---------------------------------------------------------------------------
__global__ __launch_bounds__(512)
void wsum_kernel(const float* __restrict__ h, float* __restrict__ out)
{
    __shared__ float ws[T_DIM];
    __shared__ float part[16][128];

    int tid  = threadIdx.x;
    int w    = tid >> 5;
    int lane = tid & 31;
    int c = blockIdx.x;           // 128-col chunk
    int b = blockIdx.y;

    if (tid < 128)
        reinterpret_cast<float4*>(ws)[tid] = reinterpret_cast<const float4*>(g_w)[tid];
    __syncthreads();

    const float* hp = h + (size_t)b * 1024 + c * 128 + 4 * lane;
    float4 acc = make_float4(0.f, 0.f, 0.f, 0.f);
#pragma unroll 8
    for (int i = 0; i < T_DIM / 16; ++i) {
        int t = i * 16 + w;
        float4 hv = *reinterpret_cast<const float4*>(hp + (size_t)t * (B_DIM * HU));
        float wv = ws[t];
        acc.x = fmaf(wv, hv.x, acc.x);
        acc.y = fmaf(wv, hv.y, acc.y);
        acc.z = fmaf(wv, hv.z, acc.z);
        acc.w = fmaf(wv, hv.w, acc.w);
    }
    *reinterpret_cast<float4*>(&part[w][4 * lane]) = acc;
    __syncthreads();

    if (tid < 128) {
        float s0 = part[0][tid], s1 = part[1][tid];
        float s2 = part[2][tid], s3 = part[3][tid];
#pragma unroll
        for (int q = 4; q < 16; q += 4) {
            s0 += part[q][tid];
            s1 += part[q + 1][tid];
            s2 += part[q + 2][tid];
            s3 += part[q + 3][tid];
        }
        out[b * 1024 + c * 128 + tid] = (s0 + s1) + (s2 + s3);
    }
}

// ---------------------------------------------------------------------------
extern "C" void kernel_launch(void* const* d_in, const int* in_sizes, int n_in,
                              void* d_out, int out_size)
{
    const float* si  = (const float*)d_in[0];
    const float* h   = (const float*)d_in[1];
    const float* W0  = (const float*)d_in[2];
    const float* b0  = (const float*)d_in[3];
    const float* g0  = (const float*)d_in[4];
    const float* be0 = (const float*)d_in[5];
    const float* m0  = (const float*)d_in[6];
    const float* v0  = (const float*)d_in[7];
    const float* W1  = (const float*)d_in[8];
    const float* b1  = (const float*)d_in[9];
    const float* g1  = (const float*)d_in[10];
    const float* be1 = (const float*)d_in[11];
    const float* m1  = (const float*)d_in[12];
    const float* v1  = (const float*)d_in[13];
    const float* W2  = (const float*)d_in[14];
    const float* b2  = (const float*)d_in[15];
    float* out = (float*)d_out;

    static int smem_set = 0;
    if (!smem_set) {
        cudaFuncSetAttribute(score_kernel,
                             cudaFuncAttributeMaxDynamicSharedMemorySize,
                             DYN_BYTES);
        smem_set = 1;
    }

    prep_kernel<<<B_DIM, 256>>>(si, W0, b0, g0, be0, m0, v0, b1, g1, be1, m1, v1);
    score_kernel<<<NBLK, THREADS, DYN_BYTES>>>(h, W0, W1, W2, b2);
    combine_kernel<<<1, 512>>>();
    wsum_kernel<<<dim3(8, B_DIM), 512>>>(h, out);
}

// round 17
// speedup vs baseline: 1.3616x; 1.3616x over previous
#include <cuda_runtime.h>
#include <cuda_bf16.h>
#include <math.h>
#include <stdint.h>

// ----------------------------------------------------------------------------
// Attention_13314398617962   (t=512, b=64, s=1024, hu=1024)
//   scores[t,b] = MLP(concat(si[b], h[t,b]))   (2048 -> 10 -> 5 -> 1, BN+relu)
//   a = softmax(scores.flatten())              (over all 32768)
//   ci[b,:] = sum_tau a[tau] * h[tau, b, :]    (tau < 512)
// ----------------------------------------------------------------------------

#define T_DIM 512
#define B_DIM 64
#define HU 1024
#define NROWS (T_DIM * B_DIM)   // 32768
#define RPB 32                  // rows per block in score kernel
#define NBLK (NROWS / RPB)      // 1024

// dynamic smem: red[2 groups][16 it][64 partials][10] = 20480 floats (80 KB)
#define RED_FLOATS (2 * 16 * 64 * 10)
#define DYN_BYTES  (RED_FLOATS * 4)

__device__ float g_pre0[B_DIM * 10];   // si @ W0[:1024] per b (raw dot)
__device__ float g_ep[30];             // s0[10] t0[10] s1[5] t1[5]
__device__ float g_scores[T_DIM];      // raw scores for rows < 512
__device__ float g_w[T_DIM];           // softmax weights
__device__ float g_bmax[NBLK];
__device__ float g_bsum[NBLK];

// ---------------------------------------------------------------------------
// K0: per-b si contribution (coalesced W0 reads) + folded BN constants.
// ---------------------------------------------------------------------------
__global__ __launch_bounds__(256)
void prep_kernel(const float* __restrict__ si,
                 const float* __restrict__ W0,
                 const float* __restrict__ b0,
                 const float* __restrict__ g0,
                 const float* __restrict__ be0,
                 const float* __restrict__ m0,
                 const float* __restrict__ v0,
                 const float* __restrict__ b1,
                 const float* __restrict__ g1,
                 const float* __restrict__ be1,
                 const float* __restrict__ m1,
                 const float* __restrict__ v1)
{
    __shared__ float red[64][10];

    int b = blockIdx.x;
    int tid = threadIdx.x;
    int lane = tid & 31;
    int warp = tid >> 5;

    float wv[40];
    {
        const float4* wp = reinterpret_cast<const float4*>(W0 + 4 * tid * 10);
#pragma unroll
        for (int i = 0; i < 10; ++i)
            reinterpret_cast<float4*>(wv)[i] = wp[i];
    }
    float4 sv = reinterpret_cast<const float4*>(si + b * 1024)[tid];

    float pj[10];
#pragma unroll
    for (int j = 0; j < 10; ++j) {
        float a = sv.x * wv[j];
        a = fmaf(sv.y, wv[10 + j], a);
        a = fmaf(sv.z, wv[20 + j], a);
        a = fmaf(sv.w, wv[30 + j], a);
        pj[j] = a;
    }
#pragma unroll
    for (int j = 0; j < 10; ++j) {
        pj[j] += __shfl_xor_sync(0xffffffffu, pj[j], 16);
        pj[j] += __shfl_xor_sync(0xffffffffu, pj[j], 8);
    }
    if (lane < 8) {
#pragma unroll
        for (int j = 0; j < 10; ++j) red[warp * 8 + lane][j] = pj[j];
    }
    __syncthreads();

    if (tid < 10) {
        float s = 0.f;
#pragma unroll
        for (int q = 0; q < 64; ++q) s += red[q][tid];
        g_pre0[b * 10 + tid] = s;
    }

    if (b == 0) {
        if (tid >= 32 && tid < 42) {
            int i = tid - 32;
            float s = g0[i] * (1.0f / sqrtf(v0[i] + 1e-5f));
            g_ep[i] = s;
            g_ep[10 + i] = (b0[i] - m0[i]) * s + be0[i];
        } else if (tid >= 64 && tid < 69) {
            int i = tid - 64;
            float s = g1[i] * (1.0f / sqrtf(v1[i] + 1e-5f));
            g_ep[20 + i] = s;
            g_ep[25 + i] = (b1[i] - m1[i]) * s + be1[i];
        }
    }
}

// ---------------------------------------------------------------------------
// K1: scores + per-block online softmax stats. 32 rows/block, 1024 blocks.
// R12 structure (best measured) with the SPILL FIXED:
//  - weights as 40 PLAIN f32 regs (no f32x2 packing -> saves 40 regs;
//    80 FFMA/row/thread, still under the DRAM floor)
//  - ring-4 pair prefetch (8 LDG.128 in flight/thread -> 16 KB/SM)
//  - total ~100 regs -> NO spills at the 128-reg cap of (256,2)
//  - ONE shfl round + 64-partial reduce (proven correct in R12)
// 2 row-groups x 128 threads; thread owns k = 4*ts and 512+4*ts (8 k).
// ---------------------------------------------------------------------------
__global__ __launch_bounds__(256, 2)
void score_kernel(const float* __restrict__ h,
                  const float* __restrict__ W0,
                  const float* __restrict__ W1,
                  const float* __restrict__ W2,
                  const float* __restrict__ b2)
{
    extern __shared__ float red[];            // [g][it][part64][10] 80 KB

    __shared__ float pre0s[RPB * 10];
    __shared__ float dsum[RPB * 10];
    __shared__ float epi[86];                 // s0 t0 s1 t1 W1[50] W2[5] b2

    int tid  = threadIdx.x;
    int g    = tid >> 7;
    int ts   = tid & 127;
    int lane = tid & 31;
    int wl   = (tid >> 5) & 3;                // warp within group
    int rowbase = blockIdx.x * RPB;
    int bbase   = rowbase & 63;

    if (tid < 30)                  epi[tid] = g_ep[tid];
    if (tid >= 32 && tid < 82)     epi[30 + tid - 32] = W1[tid - 32];
    if (tid >= 96 && tid < 101)    epi[80 + tid - 96] = W2[tid - 96];
    if (tid == 101)                epi[85] = b2[0];
    pre0s[tid] = g_pre0[bbase * 10 + tid];
    if (tid < 64) pre0s[256 + tid] = g_pre0[bbase * 10 + 256 + tid];

    // 80 weight floats -> wv[kk*10+j], kk 0..3 = lo half, 4..7 = hi half
    float wv[80];
    {
        const float4* wp0 = reinterpret_cast<const float4*>(W0 + (1024 + 4 * ts) * 10);
        const float4* wp1 = reinterpret_cast<const float4*>(W0 + (1536 + 4 * ts) * 10);
#pragma unroll
        for (int i = 0; i < 10; ++i)
            reinterpret_cast<float4*>(wv)[i] = wp0[i];
#pragma unroll
        for (int i = 0; i < 10; ++i)
            reinterpret_cast<float4*>(wv + 40)[i] = wp1[i];
    }

    const float* hb = h + (size_t)(rowbase + g) * 1024 + 4 * ts;
    float4 A[4], B[4];
#pragma unroll
    for (int i = 0; i < 4; ++i) {
        A[i] = *reinterpret_cast<const float4*>(hb + (size_t)i * 2048);
        B[i] = *reinterpret_cast<const float4*>(hb + (size_t)i * 2048 + 512);
    }

    __syncthreads();   // smem staging visible

    // slot base for this thread's partial (lane<16 stores)
    float* myred = red + g * 10240 + (wl * 16 + lane) * 10;

#pragma unroll
    for (int it = 0; it < 16; ++it) {
        int slot = it & 3;
        float4 ca = A[slot], cb = B[slot];
        if (it < 12) {
            const float* pn = hb + (size_t)(it + 4) * 2048;
            A[slot] = *reinterpret_cast<const float4*>(pn);
            B[slot] = *reinterpret_cast<const float4*>(pn + 512);
        }

        float pj[10];
#pragma unroll
        for (int j = 0; j < 10; ++j) {
            float a = ca.x * wv[j];
            a = fmaf(ca.y, wv[10 + j], a);
            a = fmaf(ca.z, wv[20 + j], a);
            a = fmaf(ca.w, wv[30 + j], a);
            a = fmaf(cb.x, wv[40 + j], a);
            a = fmaf(cb.y, wv[50 + j], a);
            a = fmaf(cb.z, wv[60 + j], a);
            a = fmaf(cb.w, wv[70 + j], a);
            pj[j] = a;
        }

        // ONE shfl round: lanes<16 hold sums over {lane, lane+16}
#pragma unroll
        for (int j = 0; j < 10; ++j)
            pj[j] += __shfl_xor_sync(0xffffffffu, pj[j], 16);

        if (lane < 16) {
            float2* rb = reinterpret_cast<float2*>(myred + it * 640);
#pragma unroll
            for (int p = 0; p < 5; ++p) rb[p] = make_float2(pj[2 * p], pj[2 * p + 1]);
        }
    }
    __syncthreads();

    // block reduce: 320 (row,j) sums, each over 64 partials (stride 10 floats)
#pragma unroll
    for (int pass = 0; pass < 2; ++pass) {
        int m = tid + pass * 256;
        if (m < 320) {
            int gg = m / 160;
            int rem = m - gg * 160;
            int rl = rem / 10;
            int j = rem - rl * 10;
            const float* base = red + gg * 10240 + rl * 640 + j;
            float s0 = 0.f, s1 = 0.f, s2 = 0.f, s3 = 0.f;
#pragma unroll
            for (int q = 0; q < 16; ++q) {
                s0 += base[(4 * q) * 10];
                s1 += base[(4 * q + 1) * 10];
                s2 += base[(4 * q + 2) * 10];
                s3 += base[(4 * q + 3) * 10];
            }
            dsum[(2 * rl + gg) * 10 + j] = (s0 + s1) + (s2 + s3);
        }
    }
    __syncthreads();

    // fused MLP epilogue + per-block online softmax stats (warp 0, 32 rows)
    if (tid < 32) {
        int row = rowbase + tid;
        float x0[10];
#pragma unroll
        for (int j = 0; j < 10; ++j) {
            float d = dsum[tid * 10 + j] + pre0s[tid * 10 + j];
            x0[j] = fmaxf(fmaf(d, epi[j], epi[10 + j]), 0.f);
        }
        float sc = epi[85];
#pragma unroll
        for (int i = 0; i < 5; ++i) {
            float z = 0.f;
#pragma unroll
            for (int j = 0; j < 10; ++j)
                z = fmaf(x0[j], epi[30 + j * 5 + i], z);
            float x1 = fmaxf(fmaf(z, epi[20 + i], epi[25 + i]), 0.f);
            sc = fmaf(x1, epi[80 + i], sc);
        }
        if (row < T_DIM) g_scores[row] = sc;

        float m = sc;
#pragma unroll
        for (int o = 16; o > 0; o >>= 1)
            m = fmaxf(m, __shfl_xor_sync(0xffffffffu, m, o));
        float e = expf(sc - m);
#pragma unroll
        for (int o = 16; o > 0; o >>= 1)
            e += __shfl_xor_sync(0xffffffffu, e, o);
        if (tid == 0) {
            g_bmax[blockIdx.x] = m;
            g_bsum[blockIdx.x] = e;
        }
    }
}

// ---------------------------------------------------------------------------
// K2: combine 1024 (max, expsum) pairs -> M, S; write 512 weights.
// ---------------------------------------------------------------------------
__global__ void combine_kernel()
{
    __shared__ float sm[512];
    __shared__ float MS[2];
    int tid = threadIdx.x;

    float m0v = g_bmax[tid * 2];
    float m1v = g_bmax[tid * 2 + 1];
    sm[tid] = fmaxf(m0v, m1v);
    __syncthreads();
    for (int s = 256; s > 0; s >>= 1) {
        if (tid < s) sm[tid] = fmaxf(sm[tid], sm[tid + s]);
        __syncthreads();
    }
    if (tid == 0) MS[0] = sm[0];
    __syncthreads();
    float M = MS[0];

    float ls = g_bsum[tid * 2] * expf(m0v - M)
             + g_bsum[tid * 2 + 1] * expf(m1v - M);
    sm[tid] = ls;
    __syncthreads();
    for (int s = 256; s > 0; s >>= 1) {
        if (tid < s) sm[tid] += sm[tid + s];
        __syncthreads();
    }
    if (tid == 0) MS[1] = 1.0f / sm[0];
    __syncthreads();

    g_w[tid] = expf(g_scores[tid] - M) * MS[1];
}

// ---------------------------------------------------------------------------
// K3: ci[b,:] = sum_tau w[tau] * h[tau,b,:]
// grid (8 chunks of 128 cols, 64 b) x 512 threads (16 warps, t == w mod 16).
// (best measured configuration, ~24 us)
// ---------------------------------------------------------------------------
__global__ __launch_bounds__(512)
void wsum_kernel(const float* __restrict__ h, float* __restrict__ out)
{
    __shared__ float ws[T_DIM];
    __shared__ float part[16][128];

    int tid  = threadIdx.x;
    int w    = tid >> 5;
    int lane = tid & 31;
    int c = blockIdx.x;           // 128-col chunk
    int b = blockIdx.y;

    if (tid < 128)
        reinterpret_cast<float4*>(ws)[tid] = reinterpret_cast<const float4*>(g_w)[tid];
    __syncthreads();

    const float* hp = h + (size_t)b * 1024 + c * 128 + 4 * lane;
    float4 acc = make_float4(0.f, 0.f, 0.f, 0.f);
#pragma unroll 8
    for (int i = 0; i < T_DIM / 16; ++i) {
        int t = i * 16 + w;
        float4 hv = *reinterpret_cast<const float4*>(hp + (size_t)t * (B_DIM * HU));
        float wv = ws[t];
        acc.x = fmaf(wv, hv.x, acc.x);
        acc.y = fmaf(wv, hv.y, acc.y);
        acc.z = fmaf(wv, hv.z, acc.z);
        acc.w = fmaf(wv, hv.w, acc.w);
    }
    *reinterpret_cast<float4*>(&part[w][4 * lane]) = acc;
    __syncthreads();

    if (tid < 128) {
        float s0 = part[0][tid], s1 = part[1][tid];
        float s2 = part[2][tid], s3 = part[3][tid];
#pragma unroll
        for (int q = 4; q < 16; q += 4) {
            s0 += part[q][tid];
            s1 += part[q + 1][tid];
            s2 += part[q + 2][tid];
            s3 += part[q + 3][tid];
        }
        out[b * 1024 + c * 128 + tid] = (s0 + s1) + (s2 + s3);
    }
}

// ---------------------------------------------------------------------------
extern "C" void kernel_launch(void* const* d_in, const int* in_sizes, int n_in,
                              void* d_out, int out_size)
{
    const float* si  = (const float*)d_in[0];
    const float* h   = (const float*)d_in[1];
    const float* W0  = (const float*)d_in[2];
    const float* b0  = (const float*)d_in[3];
    const float* g0  = (const float*)d_in[4];
    const float* be0 = (const float*)d_in[5];
    const float* m0  = (const float*)d_in[6];
    const float* v0  = (const float*)d_in[7];
    const float* W1  = (const float*)d_in[8];
    const float* b1  = (const float*)d_in[9];
    const float* g1  = (const float*)d_in[10];
    const float* be1 = (const float*)d_in[11];
    const float* m1  = (const float*)d_in[12];
    const float* v1  = (const float*)d_in[13];
    const float* W2  = (const float*)d_in[14];
    const float* b2  = (const float*)d_in[15];
    float* out = (float*)d_out;

    static int smem_set = 0;
    if (!smem_set) {
        cudaFuncSetAttribute(score_kernel,
                             cudaFuncAttributeMaxDynamicSharedMemorySize,
                             DYN_BYTES);
        smem_set = 1;
    }

    prep_kernel<<<B_DIM, 256>>>(si, W0, b0, g0, be0, m0, v0, b1, g1, be1, m1, v1);
    score_kernel<<<NBLK, 256, DYN_BYTES>>>(h, W0, W1, W2, b2);
    combine_kernel<<<1, 512>>>();
    wsum_kernel<<<dim3(8, B_DIM), 512>>>(h, out);
}